// round 9
// baseline (speedup 1.0000x reference)
#include <cuda_runtime.h>

// Problem constants
#define BATCH 4
#define DD 128
#define HH 128
#define WW 128
#define SLICE (HH*WW)          // 16384
#define VOL   (DD*HH*WW)       // 2097152
#define VTOT  (BATCH*VOL)      // 8388608
#define WS 11
#define RAD 5

#define C1F 1.0e-4f            // 0.01^2
#define C2F 9.0e-4f            // 0.03^2

// Separable 1-D Gaussian, window 11, sigma 1.5, normalized (compile-time).
__device__ constexpr float WL[6] = {
    0.00102838f, 0.00759876f, 0.03600077f,
    0.10936070f, 0.21300554f, 0.26601172f
};
#define WSC(t) (WL[((t) < 6) ? (t) : (10 - (t))])

// Packed intermediate: float4 = (mu1, mu2, E[x^2]+E[y^2], E[xy]) per voxel.
__device__ float4 g_m4[VTOT];
__device__ double g_acc;
__device__ unsigned g_cnt;

// ---------------------------------------------------------------------------
// Packed f32x2 helpers (Blackwell fma.rn.f32x2 / mul.rn.f32x2)
// ---------------------------------------------------------------------------
__device__ __forceinline__ float2 ffma2(float2 a, float2 b, float2 c) {
    float2 d;
    asm("fma.rn.f32x2 %0, %1, %2, %3;"
        : "=l"(reinterpret_cast<unsigned long long&>(d))
        : "l"(reinterpret_cast<unsigned long long&>(a)),
          "l"(reinterpret_cast<unsigned long long&>(b)),
          "l"(reinterpret_cast<unsigned long long&>(c)));
    return d;
}
__device__ __forceinline__ float2 fmul2(float2 a, float2 b) {
    float2 d;
    asm("mul.rn.f32x2 %0, %1, %2;"
        : "=l"(reinterpret_cast<unsigned long long&>(d))
        : "l"(reinterpret_cast<unsigned long long&>(a)),
          "l"(reinterpret_cast<unsigned long long&>(b)));
    return d;
}

// ---------------------------------------------------------------------------
// reset: zero accumulator (graph-replay safe; ordered before K2 in stream).
// ---------------------------------------------------------------------------
__global__ void reset_kernel() { g_acc = 0.0; }

// ---------------------------------------------------------------------------
// K1: y-marching x+y conv, 2 rows/step, prefetch distance 2.
// Block = 64 threads = one 64-wide x strip of one (b,z) slice.
// Grid = (xhalf=2, z=128, b=4) = 1024 blocks -> fine-grained wave balance.
// Ring of 12 x-convolved rows (4 packed fields) in registers.
// ---------------------------------------------------------------------------
#define XW   64    // output strip width
#define HW   74    // XW + 2*RAD input width

__global__ __launch_bounds__(64, 8) void conv_xy_kernel(
    const float* __restrict__ img1, const float* __restrict__ img2)
{
    __shared__ float2 sAB[2][2][HW];     // [buffer][row-in-pair][x]

    const int x  = threadIdx.x;          // 0..63
    const int xh = blockIdx.x;           // 0 or 1
    const int z  = blockIdx.y;
    const int b  = blockIdx.z;
    const int x0 = xh * XW;
    const size_t base = ((size_t)b * DD + z) * SLICE;

    float2 w2s[6];
    #pragma unroll
    for (int t = 0; t < 6; ++t) w2s[t] = make_float2(WL[t], WL[t]);
    #define W2(t) w2s[((t) < 6) ? (t) : (10 - (t))]

    // Ring of 12 x-convolved rows: rMU = (mu1,mu2), rCQ = (csum, c12).
    float2 rMU[12], rCQ[12];

    // In-flight fetch registers: [set = step&1][row-in-pair][slot], slot covers
    // idx = x + 64*slot (slot 1 active only for x < 10). Steps 0 and 1 read
    // rows -5..-2, all out of range -> zeros.
    float fa[2][2][2], fb[2][2][2];
    #pragma unroll
    for (int u = 0; u < 2; ++u)
        #pragma unroll
        for (int v = 0; v < 2; ++v)
            #pragma unroll
            for (int s = 0; s < 2; ++s) { fa[u][v][s] = 0.f; fb[u][v][s] = 0.f; }

    // 72 steps: step k handles input rows (2k-5, 2k-4), outputs y=2k-10, 2k-9.
    for (int ko = 0; ko < 12; ++ko) {
        #pragma unroll
        for (int j = 0; j < 6; ++j) {
            const int k = 6 * ko + j;

            // Publish regs fetched 2 steps ago (buffer/set = j&1, compile-time).
            float2* rb0 = sAB[j & 1][0];
            float2* rb1 = sAB[j & 1][1];
            #pragma unroll
            for (int s = 0; s < 2; ++s) {
                int idx = x + 64 * s;
                if (idx < HW) {
                    rb0[idx] = make_float2(fa[j & 1][0][s], fb[j & 1][0][s]);
                    rb1[idx] = make_float2(fa[j & 1][1][s], fb[j & 1][1][s]);
                }
            }
            __syncthreads();

            // Fetch rows for step k+2 (rows 2k-1, 2k) into the freed set.
            #pragma unroll
            for (int v = 0; v < 2; ++v) {
                int rr = 2 * k - 1 + v;
                bool okr = (unsigned)rr < HH;
                #pragma unroll
                for (int s = 0; s < 2; ++s) {
                    int idx = x + 64 * s;
                    int gx = x0 - RAD + idx;
                    bool ok = okr && (unsigned)gx < WW && idx < HW;
                    size_t gi = base + (size_t)(okr ? rr : 0) * WW
                              + (unsigned)gx % WW;
                    fa[j & 1][v][s] = ok ? __ldg(img1 + gi) : 0.f;
                    fb[j & 1][v][s] = ok ? __ldg(img2 + gi) : 0.f;
                }
            }

            // x-conv of both published rows -> ring slots 2j, 2j+1.
            {
                float2 xmu0 = make_float2(0.f, 0.f), xcv0 = make_float2(0.f, 0.f);
                float2 xmu1 = make_float2(0.f, 0.f), xcv1 = make_float2(0.f, 0.f);
                float xp0 = 0.f, xp1 = 0.f;
                #pragma unroll
                for (int t = 0; t < WS; ++t) {
                    float2 wv = W2(t);
                    float2 ab0 = rb0[x + t];
                    float2 ab1 = rb1[x + t];
                    float2 sq0 = fmul2(ab0, ab0);
                    float2 sq1 = fmul2(ab1, ab1);
                    float  pp0 = ab0.x * ab0.y;
                    float  pp1 = ab1.x * ab1.y;
                    xmu0 = ffma2(wv, ab0, xmu0);
                    xcv0 = ffma2(wv, sq0, xcv0);
                    xp0  = fmaf(WSC(t), pp0, xp0);     // FFMA-imm
                    xmu1 = ffma2(wv, ab1, xmu1);
                    xcv1 = ffma2(wv, sq1, xcv1);
                    xp1  = fmaf(WSC(t), pp1, xp1);     // FFMA-imm
                }
                rMU[2 * j]     = xmu0;
                rCQ[2 * j]     = make_float2(xcv0.x + xcv0.y, xp0);
                rMU[2 * j + 1] = xmu1;
                rCQ[2 * j + 1] = make_float2(xcv1.x + xcv1.y, xp1);
            }

            // y-conv + stores for y0 = 2k-10 (even) and y1 = y0+1.
            const int y0 = 2 * k - 10;
            if ((unsigned)y0 < HH) {
                float2 amu0 = make_float2(0.f, 0.f), acq0 = make_float2(0.f, 0.f);
                float2 amu1 = make_float2(0.f, 0.f), acq1 = make_float2(0.f, 0.f);
                #pragma unroll
                for (int t = 0; t < WS; ++t) {
                    float2 wv = W2(t);
                    const int s0 = (2 * j + t + 2) % 12;   // compile-time
                    const int s1 = (2 * j + t + 3) % 12;   // compile-time
                    amu0 = ffma2(wv, rMU[s0], amu0);
                    acq0 = ffma2(wv, rCQ[s0], acq0);
                    amu1 = ffma2(wv, rMU[s1], amu1);
                    acq1 = ffma2(wv, rCQ[s1], acq1);
                }
                size_t o0 = base + (size_t)y0 * WW + x0 + x;
                g_m4[o0]      = make_float4(amu0.x, amu0.y, acq0.x, acq0.y);
                g_m4[o0 + WW] = make_float4(amu1.x, amu1.y, acq1.x, acq1.y);
            }
        }
    }
    #undef W2
}

// ---------------------------------------------------------------------------
// K2: z-conv + SSIM + reduction + finalize. 2048 blocks x 128 threads.
// Ring in registers (compile-time slots), depth-4 prefetch, LDG.128 loads.
// ---------------------------------------------------------------------------
__device__ __forceinline__ float4 load_plane(size_t col, int zz) {
    bool ok = (unsigned)zz < DD;
    size_t idx = col + (size_t)(ok ? zz : 0) * SLICE;
    float4 v = g_m4[idx];
    if (!ok) v = make_float4(0.f, 0.f, 0.f, 0.f);
    return v;
}

__global__ __launch_bounds__(128, 5) void conv_z_ssim_kernel(float* __restrict__ out)
{
    const int x  = threadIdx.x;
    const int zc = blockIdx.x;   // z-chunk of 32: 0..3
    const int y  = blockIdx.y;   // 0..127
    const int b  = blockIdx.z;   // 0..3
    const int z0 = zc * 32;
    const size_t col = (size_t)b * VOL + (size_t)y * WW + x;

    float2 w2s[6];
    #pragma unroll
    for (int t = 0; t < 6; ++t) w2s[t] = make_float2(WL[t], WL[t]);
    #define W2(t) w2s[((t) < 6) ? (t) : (10 - (t))]

    // Ring: slot s initially holds relative plane s-5.
    float4 ring[WS];
    #pragma unroll
    for (int s = 0; s < WS; ++s) ring[s] = load_plane(col, z0 + s - RAD);

    // Prefetch pipeline, depth 4: buffers hold relative planes 6..9.
    float4 pf[4];
    #pragma unroll
    for (int q = 0; q < 4; ++q) pf[q] = load_plane(col, z0 + RAD + 1 + q);

    float fsum = 0.f;
    #pragma unroll
    for (int oz = 0; oz < 33; ++oz) {   // 33 = 3*11 so slot math is compile-time
        float2 mu = make_float2(0.f, 0.f), cq = make_float2(0.f, 0.f);
        #pragma unroll
        for (int s = 0; s < WS; ++s) {
            const int wi = ((s - oz) % WS + WS) % WS;   // compile-time
            float2 wv = W2(wi);
            mu = ffma2(wv, make_float2(ring[s].x, ring[s].y), mu);
            cq = ffma2(wv, make_float2(ring[s].z, ring[s].w), cq);
        }
        float2 musq = fmul2(mu, mu);
        float mu12  = mu.x * mu.y;
        float svar  = cq.x - musq.x - musq.y;   // sigma1^2 + sigma2^2
        float s12   = cq.y - mu12;
        float num = (2.f * mu12 + C1F) * (2.f * s12 + C2F);
        float den = (musq.x + musq.y + C1F) * (svar + C2F);
        float v = __fdividef(num, den);
        if (oz < 32) fsum += v;

        // Insert prefetched plane oz+6 (slot oz%11), refill buffer with oz+10.
        ring[oz % WS] = pf[oz & 3];
        pf[oz & 3] = load_plane(col, z0 + oz + RAD + 5);
    }
    #undef W2

    // Block reduction -> global double accumulator -> last block finalizes.
    double dsum = (double)fsum;
    #pragma unroll
    for (int off = 16; off > 0; off >>= 1)
        dsum += __shfl_down_sync(0xffffffffu, dsum, off);

    __shared__ double ssm[4];
    int wid = threadIdx.x >> 5, lid = threadIdx.x & 31;
    if (lid == 0) ssm[wid] = dsum;
    __syncthreads();
    if (threadIdx.x == 0) {
        double tot = ssm[0] + ssm[1] + ssm[2] + ssm[3];
        atomicAdd(&g_acc, tot);
        __threadfence();
        unsigned done = atomicAdd(&g_cnt, 1u);
        if (done == (unsigned)(4 * HH * BATCH - 1)) {
            out[0] = (float)(g_acc * (1.0 / (double)VTOT));
            g_cnt = 0;   // reset for next graph replay
        }
    }
}

// ---------------------------------------------------------------------------
extern "C" void kernel_launch(void* const* d_in, const int* in_sizes, int n_in,
                              void* d_out, int out_size) {
    (void)in_sizes; (void)n_in; (void)out_size;
    const float* img1 = (const float*)d_in[0];
    const float* img2 = (const float*)d_in[1];

    dim3 g1(2, DD, BATCH);                       // (2, 128, 4) = 1024 blocks
    conv_xy_kernel<<<g1, XW>>>(img1, img2);

    reset_kernel<<<1, 1>>>();

    dim3 g2(DD / 32, HH, BATCH);                 // (4, 128, 4) = 2048 blocks
    conv_z_ssim_kernel<<<g2, 128>>>((float*)d_out);
}

// round 10
// speedup vs baseline: 1.1294x; 1.1294x over previous
#include <cuda_runtime.h>

// Problem constants
#define BATCH 4
#define DD 128
#define HH 128
#define WW 128
#define SLICE (HH*WW)          // 16384
#define VOL   (DD*HH*WW)       // 2097152
#define VTOT  (BATCH*VOL)      // 8388608
#define WS 11
#define RAD 5

#define C1F 1.0e-4f            // 0.01^2
#define C2F 9.0e-4f            // 0.03^2

// Separable 1-D Gaussian, window 11, sigma 1.5, normalized (compile-time).
__device__ constexpr float WL[6] = {
    0.00102838f, 0.00759876f, 0.03600077f,
    0.10936070f, 0.21300554f, 0.26601172f
};
#define WSC(t) (WL[((t) < 6) ? (t) : (10 - (t))])

// Packed intermediate: float4 = (mu1, mu2, E[x^2]+E[y^2], E[xy]) per voxel.
__device__ float4 g_m4[VTOT];
__device__ double g_acc;
__device__ unsigned g_cnt;

// ---------------------------------------------------------------------------
// Packed f32x2 helpers (Blackwell fma.rn.f32x2 / mul.rn.f32x2)
// ---------------------------------------------------------------------------
__device__ __forceinline__ float2 ffma2(float2 a, float2 b, float2 c) {
    float2 d;
    asm("fma.rn.f32x2 %0, %1, %2, %3;"
        : "=l"(reinterpret_cast<unsigned long long&>(d))
        : "l"(reinterpret_cast<unsigned long long&>(a)),
          "l"(reinterpret_cast<unsigned long long&>(b)),
          "l"(reinterpret_cast<unsigned long long&>(c)));
    return d;
}
__device__ __forceinline__ float2 fmul2(float2 a, float2 b) {
    float2 d;
    asm("mul.rn.f32x2 %0, %1, %2;"
        : "=l"(reinterpret_cast<unsigned long long&>(d))
        : "l"(reinterpret_cast<unsigned long long&>(a)),
          "l"(reinterpret_cast<unsigned long long&>(b)));
    return d;
}

// ---------------------------------------------------------------------------
// reset: zero accumulator (graph-replay safe; ordered before K2 in stream).
// ---------------------------------------------------------------------------
__global__ void reset_kernel() { g_acc = 0.0; }

// ---------------------------------------------------------------------------
// K1: y-marching x+y conv, 2 rows/step, prefetch distance 2.
// Block = 128 threads = one full x row; handles a 64-row y-half.
// Grid = (yhalf=2, z=128, b=4) = 1024 blocks -> ~97% wave balance.
// Row pair published as one float4 (a0,b0,a1,b1): 11 LDS.128/step.
// Ring of 12 x-convolved rows (packed fields) in registers.
// ---------------------------------------------------------------------------
#define RWID 138   // 128 + 2*RAD

struct Fetch { float a0, b0, a1, b1; };

__device__ __forceinline__ Fetch fetch_rows(
    const float* __restrict__ img1, const float* __restrict__ img2,
    size_t base, int r0, int x)
{
    Fetch f;
    bool ok0 = (unsigned)r0 < HH;
    bool ok1 = (unsigned)(r0 + 1) < HH;
    size_t i0 = base + (size_t)(ok0 ? r0 : 0) * WW + x;
    size_t i1 = base + (size_t)(ok1 ? (r0 + 1) : 0) * WW + x;
    f.a0 = ok0 ? __ldg(img1 + i0) : 0.f;
    f.b0 = ok0 ? __ldg(img2 + i0) : 0.f;
    f.a1 = ok1 ? __ldg(img1 + i1) : 0.f;
    f.b1 = ok1 ? __ldg(img2 + i1) : 0.f;
    return f;
}

__global__ __launch_bounds__(128, 4) void conv_xy_kernel(
    const float* __restrict__ img1, const float* __restrict__ img2)
{
    __shared__ float4 sAB[2][RWID];      // [buffer][x]: (a0,b0,a1,b1)

    const int x  = threadIdx.x;          // 0..127
    const int yh = blockIdx.x;           // 0 or 1
    const int z  = blockIdx.y;
    const int b  = blockIdx.z;
    const int y0 = yh * 64;
    const size_t base = ((size_t)b * DD + z) * SLICE;

    // Zero the x halos once (never overwritten afterwards).
    if (x < RAD) {
        #pragma unroll
        for (int u = 0; u < 2; ++u) {
            sAB[u][x]       = make_float4(0.f, 0.f, 0.f, 0.f);
            sAB[u][133 + x] = make_float4(0.f, 0.f, 0.f, 0.f);
        }
    }
    __syncthreads();

    float2 w2s[6];
    #pragma unroll
    for (int t = 0; t < 6; ++t) w2s[t] = make_float2(WL[t], WL[t]);
    #define W2(t) w2s[((t) < 6) ? (t) : (10 - (t))]

    // Ring of 12 x-convolved rows: rMU = (mu1,mu2), rCQ = (csum, c12).
    float2 rMU[12], rCQ[12];

    // Prefetch steps 0 and 1 (rows y0-5..y0-2; real rows for yh=1).
    Fetch f[2];
    f[0] = fetch_rows(img1, img2, base, y0 - 5, x);
    f[1] = fetch_rows(img1, img2, base, y0 - 3, x);

    // One step: publish f[j&1], prefetch k+2, x-conv -> slots (2j, 2j+1),
    // y-conv -> outputs y0+2k-10, y0+2k-9 (when k >= 5).
    #define STEP(k, j, DO_FETCH)                                              \
    {                                                                         \
        float4* rowbuf = sAB[(j) & 1];                                        \
        rowbuf[x + RAD] = make_float4(f[(j) & 1].a0, f[(j) & 1].b0,           \
                                      f[(j) & 1].a1, f[(j) & 1].b1);          \
        __syncthreads();                                                      \
        if (DO_FETCH)                                                         \
            f[(j) & 1] = fetch_rows(img1, img2, base, y0 + 2 * (k) - 1, x);   \
        float2 xmu0 = make_float2(0.f, 0.f), xcv0 = make_float2(0.f, 0.f);    \
        float2 xmu1 = make_float2(0.f, 0.f), xcv1 = make_float2(0.f, 0.f);    \
        float2 xp01 = make_float2(0.f, 0.f);                                  \
        _Pragma("unroll")                                                     \
        for (int t = 0; t < WS; ++t) {                                        \
            float2 wv = W2(t);                                                \
            float4 v4 = rowbuf[x + t];                                        \
            float2 ab0 = make_float2(v4.x, v4.y);                             \
            float2 ab1 = make_float2(v4.z, v4.w);                             \
            float2 sq0 = fmul2(ab0, ab0);                                     \
            float2 sq1 = fmul2(ab1, ab1);                                     \
            float2 pp  = make_float2(v4.x * v4.y, v4.z * v4.w);               \
            xmu0 = ffma2(wv, ab0, xmu0);                                      \
            xcv0 = ffma2(wv, sq0, xcv0);                                      \
            xmu1 = ffma2(wv, ab1, xmu1);                                      \
            xcv1 = ffma2(wv, sq1, xcv1);                                      \
            xp01 = ffma2(wv, pp, xp01);                                       \
        }                                                                     \
        rMU[(2 * (j)) % 12]     = xmu0;                                       \
        rCQ[(2 * (j)) % 12]     = make_float2(xcv0.x + xcv0.y, xp01.x);       \
        rMU[(2 * (j) + 1) % 12] = xmu1;                                       \
        rCQ[(2 * (j) + 1) % 12] = make_float2(xcv1.x + xcv1.y, xp01.y);       \
        if ((k) >= 5) {                                                       \
            float2 amu0 = make_float2(0.f, 0.f), acq0 = make_float2(0.f, 0.f);\
            float2 amu1 = make_float2(0.f, 0.f), acq1 = make_float2(0.f, 0.f);\
            _Pragma("unroll")                                                 \
            for (int t = 0; t < WS; ++t) {                                    \
                float2 wv = W2(t);                                            \
                const int s0 = (2 * (j) + t + 2) % 12;                        \
                const int s1 = (2 * (j) + t + 3) % 12;                        \
                amu0 = ffma2(wv, rMU[s0], amu0);                              \
                acq0 = ffma2(wv, rCQ[s0], acq0);                              \
                amu1 = ffma2(wv, rMU[s1], amu1);                              \
                acq1 = ffma2(wv, rCQ[s1], acq1);                              \
            }                                                                 \
            size_t o0 = base + (size_t)(y0 + 2 * (k) - 10) * WW + x;          \
            g_m4[o0]      = make_float4(amu0.x, amu0.y, acq0.x, acq0.y);      \
            g_m4[o0 + WW] = make_float4(amu1.x, amu1.y, acq1.x, acq1.y);      \
        }                                                                     \
    }

    // Main: 36 steps (k = 6*ko + j), then 1 epilogue step (k=36, phase j=0).
    for (int ko = 0; ko < 6; ++ko) {
        #pragma unroll
        for (int j = 0; j < 6; ++j) {
            const int k = 6 * ko + j;
            STEP(k, j, true)
        }
    }
    STEP(36, 0, false)
    #undef STEP
    #undef W2
}

// ---------------------------------------------------------------------------
// K2: z-conv + SSIM + reduction + finalize. 2048 blocks x 128 threads.
// Ring in registers (compile-time slots), depth-4 prefetch, LDG.128 loads.
// ---------------------------------------------------------------------------
__device__ __forceinline__ float4 load_plane(size_t col, int zz) {
    bool ok = (unsigned)zz < DD;
    size_t idx = col + (size_t)(ok ? zz : 0) * SLICE;
    float4 v = g_m4[idx];
    if (!ok) v = make_float4(0.f, 0.f, 0.f, 0.f);
    return v;
}

__global__ __launch_bounds__(128, 5) void conv_z_ssim_kernel(float* __restrict__ out)
{
    const int x  = threadIdx.x;
    const int zc = blockIdx.x;   // z-chunk of 32: 0..3
    const int y  = blockIdx.y;   // 0..127
    const int b  = blockIdx.z;   // 0..3
    const int z0 = zc * 32;
    const size_t col = (size_t)b * VOL + (size_t)y * WW + x;

    float2 w2s[6];
    #pragma unroll
    for (int t = 0; t < 6; ++t) w2s[t] = make_float2(WL[t], WL[t]);
    #define W2(t) w2s[((t) < 6) ? (t) : (10 - (t))]

    // Ring: slot s initially holds relative plane s-5.
    float4 ring[WS];
    #pragma unroll
    for (int s = 0; s < WS; ++s) ring[s] = load_plane(col, z0 + s - RAD);

    // Prefetch pipeline, depth 4: buffers hold relative planes 6..9.
    float4 pf[4];
    #pragma unroll
    for (int q = 0; q < 4; ++q) pf[q] = load_plane(col, z0 + RAD + 1 + q);

    float fsum = 0.f;
    #pragma unroll
    for (int oz = 0; oz < 33; ++oz) {   // 33 = 3*11 so slot math is compile-time
        float2 mu = make_float2(0.f, 0.f), cq = make_float2(0.f, 0.f);
        #pragma unroll
        for (int s = 0; s < WS; ++s) {
            const int wi = ((s - oz) % WS + WS) % WS;   // compile-time
            float2 wv = W2(wi);
            mu = ffma2(wv, make_float2(ring[s].x, ring[s].y), mu);
            cq = ffma2(wv, make_float2(ring[s].z, ring[s].w), cq);
        }
        float2 musq = fmul2(mu, mu);
        float mu12  = mu.x * mu.y;
        float svar  = cq.x - musq.x - musq.y;   // sigma1^2 + sigma2^2
        float s12   = cq.y - mu12;
        float num = (2.f * mu12 + C1F) * (2.f * s12 + C2F);
        float den = (musq.x + musq.y + C1F) * (svar + C2F);
        float v = __fdividef(num, den);
        if (oz < 32) fsum += v;

        // Insert prefetched plane oz+6 (slot oz%11), refill buffer with oz+10.
        ring[oz % WS] = pf[oz & 3];
        pf[oz & 3] = load_plane(col, z0 + oz + RAD + 5);
    }
    #undef W2

    // Block reduction -> global double accumulator -> last block finalizes.
    double dsum = (double)fsum;
    #pragma unroll
    for (int off = 16; off > 0; off >>= 1)
        dsum += __shfl_down_sync(0xffffffffu, dsum, off);

    __shared__ double ssm[4];
    int wid = threadIdx.x >> 5, lid = threadIdx.x & 31;
    if (lid == 0) ssm[wid] = dsum;
    __syncthreads();
    if (threadIdx.x == 0) {
        double tot = ssm[0] + ssm[1] + ssm[2] + ssm[3];
        atomicAdd(&g_acc, tot);
        __threadfence();
        unsigned done = atomicAdd(&g_cnt, 1u);
        if (done == (unsigned)(4 * HH * BATCH - 1)) {
            out[0] = (float)(g_acc * (1.0 / (double)VTOT));
            g_cnt = 0;   // reset for next graph replay
        }
    }
}

// ---------------------------------------------------------------------------
extern "C" void kernel_launch(void* const* d_in, const int* in_sizes, int n_in,
                              void* d_out, int out_size) {
    (void)in_sizes; (void)n_in; (void)out_size;
    const float* img1 = (const float*)d_in[0];
    const float* img2 = (const float*)d_in[1];

    dim3 g1(2, DD, BATCH);                       // (2, 128, 4) = 1024 blocks
    conv_xy_kernel<<<g1, 128>>>(img1, img2);

    reset_kernel<<<1, 1>>>();

    dim3 g2(DD / 32, HH, BATCH);                 // (4, 128, 4) = 2048 blocks
    conv_z_ssim_kernel<<<g2, 128>>>((float*)d_out);
}